// round 4
// baseline (speedup 1.0000x reference)
#include <cuda_runtime.h>

#define N_NODES 100000
#define N_EDGES 3200000
#define F_IN    512
#define NH      16
#define NC      3

// ---------------- scratch (device globals; no allocations allowed) ----------
// NOTE: these are referenced ONLY from device code. Passing a __device__
// symbol as a host-side kernel argument takes the HOST shadow address, which
// on GB300 (ATS, pageableMemoryAccess=1) silently dereferences host memory
// instead of faulting — that was the Round-2 correctness bug.
__device__ float g_deg_out[N_NODES];
__device__ float g_deg_in [N_NODES];
__device__ float g_norm_src[N_NODES];
__device__ float g_norm_dst[N_NODES];
__device__ float g_h1  [(size_t)N_NODES * NH];   // (feat*ns)@W1
__device__ float g_agg1[(size_t)N_NODES * NH];
__device__ float g_x   [(size_t)N_NODES * NH];   // relu(agg1*nd+b1)*ns
__device__ float g_agg2[(size_t)N_NODES * NH];
__device__ float g_W2f [NH * NC];                 // W2 @ Wfc
__device__ float g_b2f [NC];                      // b2 @ Wfc + bfc
__device__ int   g_idx64;                         // 1 if indices are int64

// ---------------- index dtype detection (int64 vs int32) --------------------
__global__ void k_detect(const int* __restrict__ src_as_i32) {
    // If indices are int64 (values < 2^31), every odd 32-bit word is 0.
    // If int32, odd words are random node ids: P(all 64 zero) ~ 0.
    int any = 0;
    #pragma unroll
    for (int j = 0; j < 64; j++) any |= src_as_i32[2 * j + 1];
    g_idx64 = (any == 0) ? 1 : 0;
}

__device__ __forceinline__ int load_idx(const void* p, int i, int is64) {
    return is64 ? (int)((const long long*)p)[i] : ((const int*)p)[i];
}

// ---------------- zero accumulators -----------------------------------------
__global__ void k_zero() {
    int i = blockIdx.x * blockDim.x + threadIdx.x;
    const int tot = N_NODES * NH;
    if (i < tot) { g_agg1[i] = 0.f; g_agg2[i] = 0.f; }
    if (i < N_NODES) { g_deg_out[i] = 0.f; g_deg_in[i] = 0.f; }
}

// ---------------- degrees ----------------------------------------------------
__global__ void k_deg(const void* __restrict__ src, const void* __restrict__ dst) {
    int i = blockIdx.x * blockDim.x + threadIdx.x;
    if (i >= N_EDGES) return;
    int is64 = g_idx64;
    int s = load_idx(src, i, is64);
    int d = load_idx(dst, i, is64);
    atomicAdd(&g_deg_out[s], 1.f);
    atomicAdd(&g_deg_in [d], 1.f);
}

__global__ void k_norm() {
    int i = blockIdx.x * blockDim.x + threadIdx.x;
    if (i >= N_NODES) return;
    g_norm_src[i] = rsqrtf(fmaxf(g_deg_out[i], 1.f));
    g_norm_dst[i] = rsqrtf(fmaxf(g_deg_in [i], 1.f));
}

// ---------------- GEMM1: h1 = (feat @ W1) * norm_src  [100000x512 @ 512x16] --
// Block: 256 threads = 128 nodes x 2 output-halves. W1 resident in smem
// (broadcast across lanes), features staged in 128-wide K chunks.
// Inner step per thread: 1 LDS(f) + pack + 2 LDS.128(W pairs) + 4 fma.rn.f32x2.
#define GB 128
#define KC 128
#define SMEM_GEMM ((F_IN * NH + GB * (KC + 4)) * 4)

__global__ __launch_bounds__(256, 2)
void k_gemm1(const float* __restrict__ feat, const float* __restrict__ W1) {
    extern __shared__ float smem[];
    float* sW = smem;                    // [512][16]
    float* sF = smem + F_IN * NH;        // [128][KC+4]

    const int tid = threadIdx.x;
    const int nl  = tid >> 1;            // local node 0..127
    const int oh  = tid & 1;             // output half (8 outputs each)
    const int n0  = blockIdx.x * GB;

    // load W1 (32KB) cooperatively
    {
        const float4* W4 = (const float4*)W1;
        float4* sW4 = (float4*)sW;
        #pragma unroll
        for (int t = tid; t < F_IN * NH / 4; t += 256) sW4[t] = W4[t];
    }

    unsigned long long A0 = 0ull, A1 = 0ull, A2 = 0ull, A3 = 0ull;

    for (int kc = 0; kc < F_IN; kc += KC) {
        __syncthreads();
        // stage feat[n0..n0+128)[kc..kc+KC)
        {
            const float4* f4 = (const float4*)feat;
            #pragma unroll
            for (int t = tid; t < GB * (KC / 4); t += 256) {
                int node = t >> 5;           // KC/4 == 32
                int q    = t & 31;
                int n    = n0 + node;
                float4 v = make_float4(0.f, 0.f, 0.f, 0.f);
                if (n < N_NODES)
                    v = f4[(size_t)n * (F_IN / 4) + (kc >> 2) + q];
                *(float4*)&sF[node * (KC + 4) + q * 4] = v;
            }
        }
        __syncthreads();

        const float* frow = &sF[nl * (KC + 4)];
        #pragma unroll 4
        for (int kk = 0; kk < KC; kk++) {
            float f = frow[kk];
            unsigned long long fp;
            asm("mov.b64 %0, {%1, %1};" : "=l"(fp) : "f"(f));
            const float* wp = &sW[(kc + kk) * NH + oh * 8];
            ulonglong2 wa = *(const ulonglong2*)wp;        // pairs (o0,o1),(o2,o3)
            ulonglong2 wb = *(const ulonglong2*)(wp + 4);  // pairs (o4,o5),(o6,o7)
            asm("fma.rn.f32x2 %0, %1, %2, %0;" : "+l"(A0) : "l"(fp), "l"(wa.x));
            asm("fma.rn.f32x2 %0, %1, %2, %0;" : "+l"(A1) : "l"(fp), "l"(wa.y));
            asm("fma.rn.f32x2 %0, %1, %2, %0;" : "+l"(A2) : "l"(fp), "l"(wb.x));
            asm("fma.rn.f32x2 %0, %1, %2, %0;" : "+l"(A3) : "l"(fp), "l"(wb.y));
        }
    }

    int n = n0 + nl;
    if (n < N_NODES) {
        float ns = g_norm_src[n];
        float2 v0 = *(float2*)&A0, v1 = *(float2*)&A1;
        float2 v2 = *(float2*)&A2, v3 = *(float2*)&A3;
        float4* dst4 = (float4*)&g_h1[(size_t)n * NH + oh * 8];
        dst4[0] = make_float4(v0.x * ns, v0.y * ns, v1.x * ns, v1.y * ns);
        dst4[1] = make_float4(v2.x * ns, v2.y * ns, v3.x * ns, v3.y * ns);
    }
}

// ---------------- edge aggregation: acc[dst] += tab[src]  (16 floats) --------
// Template selects the table/accumulator pair at COMPILE time — device code
// references the __device__ globals directly (no host-passed symbol pointers).
__device__ __forceinline__ void red4(float* p, float4 v) {
    asm volatile("red.global.add.v4.f32 [%0], {%1,%2,%3,%4};"
                 :: "l"(p), "f"(v.x), "f"(v.y), "f"(v.z), "f"(v.w) : "memory");
}

template <int LAYER>
__global__ void k_edge(const void* __restrict__ src, const void* __restrict__ dst) {
    const float* tab = (LAYER == 1) ? g_h1 : g_x;
    float*       acc = (LAYER == 1) ? g_agg1 : g_agg2;
    int i = blockIdx.x * blockDim.x + threadIdx.x;
    if (i >= N_EDGES) return;
    int is64 = g_idx64;
    int s = load_idx(src, i, is64);
    int d = load_idx(dst, i, is64);
    const float4* t4 = (const float4*)(tab + (size_t)s * NH);
    float4 v0 = __ldg(t4 + 0), v1 = __ldg(t4 + 1);
    float4 v2 = __ldg(t4 + 2), v3 = __ldg(t4 + 3);
    float* base = acc + (size_t)d * NH;
    red4(base + 0,  v0);
    red4(base + 4,  v1);
    red4(base + 8,  v2);
    red4(base + 12, v3);
}

// ---------------- x = relu(agg1*nd + b1) * ns  (fold next layer's ns in) -----
__global__ void k_x(const float* __restrict__ b1) {
    int i = blockIdx.x * blockDim.x + threadIdx.x;   // one float4 per thread
    if (i >= N_NODES * (NH / 4)) return;
    int n = i >> 2, q = i & 3;
    float4 a = ((const float4*)g_agg1)[i];
    float nd = g_norm_dst[n];
    float ns = g_norm_src[n];
    float4 b = ((const float4*)b1)[q];
    float4 r;
    r.x = fmaxf(fmaf(a.x, nd, b.x), 0.f) * ns;
    r.y = fmaxf(fmaf(a.y, nd, b.y), 0.f) * ns;
    r.z = fmaxf(fmaf(a.z, nd, b.z), 0.f) * ns;
    r.w = fmaxf(fmaf(a.w, nd, b.w), 0.f) * ns;
    ((float4*)g_x)[i] = r;
}

// ---------------- W2f = W2 @ Wfc [16x3], b2f = b2 @ Wfc + bfc ----------------
__global__ void k_w2f(const float* __restrict__ W2, const float* __restrict__ b2,
                      const float* __restrict__ Wfc, const float* __restrict__ bfc) {
    int t = threadIdx.x;
    if (t < NH * NC) {
        int h = t / NC, c = t % NC;
        float s = 0.f;
        #pragma unroll 8
        for (int k = 0; k < 128; k++) s = fmaf(W2[h * 128 + k], Wfc[k * NC + c], s);
        g_W2f[t] = s;
    } else if (t < NH * NC + NC) {
        int c = t - NH * NC;
        float s = bfc[c];
        #pragma unroll 8
        for (int k = 0; k < 128; k++) s = fmaf(b2[k], Wfc[k * NC + c], s);
        g_b2f[c] = s;
    }
}

// ---------------- out = nd * (agg2 @ W2f) + b2f ------------------------------
__global__ void k_out(float* __restrict__ out) {
    __shared__ float sw[NH * NC + NC];
    if (threadIdx.x < NH * NC + NC)
        sw[threadIdx.x] = (threadIdx.x < NH * NC) ? g_W2f[threadIdx.x]
                                                  : g_b2f[threadIdx.x - NH * NC];
    __syncthreads();
    int n = blockIdx.x * blockDim.x + threadIdx.x;
    if (n >= N_NODES) return;
    const float4* a4 = (const float4*)(g_agg2 + (size_t)n * NH);
    float4 A[4] = {a4[0], a4[1], a4[2], a4[3]};
    const float* af = (const float*)A;
    float nd = g_norm_dst[n];
    float s0 = 0.f, s1 = 0.f, s2 = 0.f;
    #pragma unroll
    for (int h = 0; h < NH; h++) {
        float a = af[h];
        s0 = fmaf(a, sw[h * 3 + 0], s0);
        s1 = fmaf(a, sw[h * 3 + 1], s1);
        s2 = fmaf(a, sw[h * 3 + 2], s2);
    }
    out[(size_t)n * 3 + 0] = fmaf(nd, s0, sw[48]);
    out[(size_t)n * 3 + 1] = fmaf(nd, s1, sw[49]);
    out[(size_t)n * 3 + 2] = fmaf(nd, s2, sw[50]);
}

// ---------------- launch ------------------------------------------------------
extern "C" void kernel_launch(void* const* d_in, const int* in_sizes, int n_in,
                              void* d_out, int out_size) {
    const float* feat = (const float*)d_in[0];
    const void*  src  = d_in[1];
    const void*  dst  = d_in[2];
    const float* W1   = (const float*)d_in[3];
    const float* b1   = (const float*)d_in[4];
    const float* W2   = (const float*)d_in[5];
    const float* b2   = (const float*)d_in[6];
    const float* Wfc  = (const float*)d_in[7];
    const float* bfc  = (const float*)d_in[8];
    float* out = (float*)d_out;

    cudaFuncSetAttribute(k_gemm1, cudaFuncAttributeMaxDynamicSharedMemorySize,
                         SMEM_GEMM);

    const int EB = (N_EDGES + 255) / 256;            // 12500
    const int NB = (N_NODES + 255) / 256;            // 391

    k_detect  <<<1, 1>>>((const int*)src);
    k_zero    <<<(N_NODES * NH + 255) / 256, 256>>>();
    k_deg     <<<EB, 256>>>(src, dst);
    k_norm    <<<NB, 256>>>();
    k_gemm1   <<<(N_NODES + GB - 1) / GB, 256, SMEM_GEMM>>>(feat, W1);
    k_edge<1> <<<EB, 256>>>(src, dst);
    k_x       <<<(N_NODES * (NH / 4) + 255) / 256, 256>>>(b1);
    k_w2f     <<<1, 64>>>(W2, b2, Wfc, bfc);
    k_edge<2> <<<EB, 256>>>(src, dst);
    k_out     <<<NB, 256>>>(out);
}